// round 9
// baseline (speedup 1.0000x reference)
#include <cuda_runtime.h>
#include <cuda_bf16.h>

#define B_DIM 512
#define P_DIM 512
#define F_DIM 1024
#define EPS_T 1e-8f

#define SPLITK 16
#define KC 64                   // u16 k-extent per unit
#define BM 128
#define BN 64
#define NTILES 32               // (512/128) x (512/64)
#define NUNITS (NTILES * SPLITK)    // 512
#define GRID_MAIN 296
#define QSCALE 65535.0f
#define KPITCH 72               // smem row pitch in u16 (144B)

#define XS_BUF (BM * KPITCH)    // 9216 u16
#define WS_BUF (BN * KPITCH)    // 4608 u16
#define SMEM_U16 (2 * XS_BUF + 2 * WS_BUF)
#define SMEM_BYTES (SMEM_U16 * 2)   // 55,296 B

// Scratch (static device globals — no allocation allowed)
__device__ __align__(16) unsigned short g_qx[B_DIM * F_DIM];  // u16 sigmoid(x)
__device__ __align__(16) unsigned short g_qw[P_DIM * F_DIM];  // u16 sigmoid(w)
__device__ __align__(16) float g_S[B_DIM + P_DIM];            // fp32 row sums
__device__ float g_part[SPLITK * B_DIM * P_DIM];              // split-K partials
__device__ int   g_ctr;                                       // work counter

// ---------------------------------------------------------------------------
// Kernel 1: sigmoid -> u16 quantize + row sums. One WARP per row, MLP=8.
// 256 blocks x 128 threads. No smem, no block sync. Also resets g_ctr.
// ---------------------------------------------------------------------------
__global__ __launch_bounds__(128) void prep_kernel(
    const float* __restrict__ x, const float* __restrict__ w)
{
    if (blockIdx.x == 0 && threadIdx.x == 0) g_ctr = 0;

    int warp = threadIdx.x >> 5;
    int lane = threadIdx.x & 31;
    int row = blockIdx.x * 4 + warp;      // 0..1023 combined row

    const float* src;
    unsigned short* dq;
    if (row < B_DIM) {
        src = x + (size_t)row * F_DIM;
        dq  = g_qx + (size_t)row * F_DIM;
    } else {
        src = w + (size_t)(row - B_DIM) * F_DIM;
        dq  = g_qw + (size_t)(row - B_DIM) * F_DIM;
    }

    float4 v[8];
    #pragma unroll
    for (int k = 0; k < 8; k++)
        v[k] = reinterpret_cast<const float4*>(src)[lane + 32 * k];

    float sum = 0.f;
    #pragma unroll
    for (int k = 0; k < 8; k++) {
        float s0 = 1.0f / (1.0f + __expf(-v[k].x));
        float s1 = 1.0f / (1.0f + __expf(-v[k].y));
        float s2 = 1.0f / (1.0f + __expf(-v[k].z));
        float s3 = 1.0f / (1.0f + __expf(-v[k].w));
        sum += (s0 + s1) + (s2 + s3);
        unsigned q0 = __float2uint_rn(s0 * QSCALE);
        unsigned q1 = __float2uint_rn(s1 * QSCALE);
        unsigned q2 = __float2uint_rn(s2 * QSCALE);
        unsigned q3 = __float2uint_rn(s3 * QSCALE);
        reinterpret_cast<uint2*>(dq)[lane + 32 * k] =
            make_uint2(q0 | (q1 << 16), q2 | (q3 << 16));
    }

    #pragma unroll
    for (int o = 16; o > 0; o >>= 1)
        sum += __shfl_xor_sync(0xFFFFFFFFu, sum, o);
    if (lane == 0)
        g_S[row] = sum;
}

// ---------------------------------------------------------------------------
// Main compute: one KC=64 chunk-set from one smem buffer. 8x4 register tile.
// ---------------------------------------------------------------------------
__device__ __forceinline__ void compute_unit(
    const unsigned short* __restrict__ xb,
    const unsigned short* __restrict__ wb,
    int tx, int ty, unsigned acc[8][4])
{
    #pragma unroll 2
    for (int c = 0; c < 8; c++) {         // 8 u16 of k per chunk
        uint4 xq[8], wq[4];
        #pragma unroll
        for (int i = 0; i < 8; i++)
            xq[i] = *reinterpret_cast<const uint4*>(xb + (ty + 16 * i) * KPITCH + c * 8);
        #pragma unroll
        for (int j = 0; j < 4; j++)
            wq[j] = *reinterpret_cast<const uint4*>(wb + (tx + 16 * j) * KPITCH + c * 8);

        #pragma unroll
        for (int i = 0; i < 8; i++)
            #pragma unroll
            for (int j = 0; j < 4; j++) {
                acc[i][j] = __dp2a_lo(__vminu2(xq[i].x, wq[j].x), 0x0101u, acc[i][j]);
                acc[i][j] = __dp2a_lo(__vminu2(xq[i].y, wq[j].y), 0x0101u, acc[i][j]);
                acc[i][j] = __dp2a_lo(__vminu2(xq[i].z, wq[j].z), 0x0101u, acc[i][j]);
                acc[i][j] = __dp2a_lo(__vminu2(xq[i].w, wq[j].w), 0x0101u, acc[i][j]);
            }
    }
}

// ---------------------------------------------------------------------------
// Kernel 2: persistent u16 min-sum. Unit = 128x64 tile x KC=64. 512 units.
// Dynamic queue, cross-unit double buffer, register prefetch.
// ---------------------------------------------------------------------------
__global__ __launch_bounds__(256, 2) void tversky_main_kernel()
{
    extern __shared__ unsigned short smem[];
    unsigned short* xs0 = smem;                   // [2][BM][KPITCH]
    unsigned short* ws0 = smem + 2 * XS_BUF;      // [2][BN][KPITCH]
    __shared__ int s_u;

    int tid = threadIdx.x;
    int tx = tid & 15;            // N: tx + 16j
    int ty = tid >> 4;            // M: ty + 16i
    int r0 = tid >> 3;            // loader row 0..31
    int seg = tid & 7;            // 16B segment

    const uint4* xg4 = reinterpret_cast<const uint4*>(g_qx);
    const uint4* wg4 = reinterpret_cast<const uint4*>(g_qw);

    if (tid == 0) s_u = atomicAdd(&g_ctr, 1);
    __syncthreads();
    int u = s_u;

    if (u < NUNITS) {             // prologue: stage first unit into buf 0
        int tile = u >> 4, split = u & 15;
        int m0 = (tile >> 3) * BM, n0 = (tile & 7) * BN;
        int kb4 = split * 8;
        #pragma unroll
        for (int q = 0; q < 4; q++) {
            uint4 a = xg4[(m0 + r0 + 32 * q) * 128 + kb4 + seg];
            *reinterpret_cast<uint4*>(xs0 + (r0 + 32 * q) * KPITCH + seg * 8) = a;
        }
        #pragma unroll
        for (int q = 0; q < 2; q++) {
            uint4 b = wg4[(n0 + r0 + 32 * q) * 128 + kb4 + seg];
            *reinterpret_cast<uint4*>(ws0 + (r0 + 32 * q) * KPITCH + seg * 8) = b;
        }
    }
    int cur = 0;

    while (u < NUNITS) {
        if (tid == 0) s_u = atomicAdd(&g_ctr, 1);
        __syncthreads();          // tile(cur) + s_u visible
        int un = s_u;

        // prefetch next unit into registers (hidden behind compute)
        uint4 pa[4], pb[2];
        if (un < NUNITS) {
            int tile = un >> 4, split = un & 15;
            int m0 = (tile >> 3) * BM, n0 = (tile & 7) * BN;
            int kb4 = split * 8;
            #pragma unroll
            for (int q = 0; q < 4; q++)
                pa[q] = xg4[(m0 + r0 + 32 * q) * 128 + kb4 + seg];
            #pragma unroll
            for (int q = 0; q < 2; q++)
                pb[q] = wg4[(n0 + r0 + 32 * q) * 128 + kb4 + seg];
        }

        unsigned acc[8][4];
        #pragma unroll
        for (int i = 0; i < 8; i++)
            #pragma unroll
            for (int j = 0; j < 4; j++) acc[i][j] = 0u;

        compute_unit(xs0 + cur * XS_BUF, ws0 + cur * WS_BUF, tx, ty, acc);

        if (un < NUNITS) {        // stage next unit into other buffer
            int nb = cur ^ 1;
            #pragma unroll
            for (int q = 0; q < 4; q++)
                *reinterpret_cast<uint4*>(xs0 + nb * XS_BUF + (r0 + 32 * q) * KPITCH + seg * 8) = pa[q];
            #pragma unroll
            for (int q = 0; q < 2; q++)
                *reinterpret_cast<uint4*>(ws0 + nb * WS_BUF + (r0 + 32 * q) * KPITCH + seg * 8) = pb[q];
        }

        // write split-K partials for unit u (exact u32 counts as fp32)
        {
            int tile = u >> 4, split = u & 15;
            int m0 = (tile >> 3) * BM, n0 = (tile & 7) * BN;
            float* pbase = g_part + ((size_t)split * B_DIM + m0) * P_DIM + n0;
            #pragma unroll
            for (int i = 0; i < 8; i++)
                #pragma unroll
                for (int j = 0; j < 4; j++)
                    pbase[(size_t)(ty + 16 * i) * P_DIM + tx + 16 * j] = (float)acc[i][j];
        }

        u = un;
        cur ^= 1;
        __syncthreads();          // protect s_u + buffer reuse
    }
}

// ---------------------------------------------------------------------------
// Kernel 3: combine 16 split-K partials (scale 1/65535) + Tversky epilogue.
// ---------------------------------------------------------------------------
__global__ __launch_bounds__(256) void finalize_kernel(
    const float* __restrict__ bias,
    const float* __restrict__ alpha,
    const float* __restrict__ beta,
    float* __restrict__ out)
{
    int t4 = blockIdx.x * 256 + threadIdx.x;   // float4 id, 0..65535
    int m  = t4 >> 7;
    int n4 = t4 & 127;

    const float4* pp = reinterpret_cast<const float4*>(g_part) + t4;
    float4 I = make_float4(0.f, 0.f, 0.f, 0.f);
    #pragma unroll
    for (int s = 0; s < SPLITK; s++) {
        float4 v = pp[(size_t)s * (B_DIM * P_DIM / 4)];
        I.x += v.x; I.y += v.y; I.z += v.z; I.w += v.w;
    }
    const float inv = 1.0f / QSCALE;
    I.x *= inv; I.y *= inv; I.z *= inv; I.w *= inv;

    float Sx = g_S[m];
    float4 Sw = reinterpret_cast<const float4*>(g_S + B_DIM)[n4];

    float a = *alpha;
    float b = *beta;
    float4 bs = reinterpret_cast<const float4*>(bias)[n4];

    float4 o;
    o.x = I.x / (I.x + a * (Sx - I.x) + b * (Sw.x - I.x) + EPS_T) + bs.x;
    o.y = I.y / (I.y + a * (Sx - I.y) + b * (Sw.y - I.y) + EPS_T) + bs.y;
    o.z = I.z / (I.z + a * (Sx - I.z) + b * (Sw.z - I.z) + EPS_T) + bs.z;
    o.w = I.w / (I.w + a * (Sx - I.w) + b * (Sw.w - I.w) + EPS_T) + bs.w;

    reinterpret_cast<float4*>(out)[t4] = o;
}

// ---------------------------------------------------------------------------
extern "C" void kernel_launch(void* const* d_in, const int* in_sizes, int n_in,
                              void* d_out, int out_size)
{
    const float* x      = (const float*)d_in[0];   // (512, 1024)
    const float* weight = (const float*)d_in[1];   // (512, 1024)
    const float* bias   = (const float*)d_in[2];   // (512,)
    const float* alpha  = (const float*)d_in[3];   // scalar
    const float* beta   = (const float*)d_in[4];   // scalar
    float* out = (float*)d_out;                    // (512, 512)

    static bool attr_set = false;                  // host-side only; not device state
    if (!attr_set) {
        cudaFuncSetAttribute(tversky_main_kernel,
                             cudaFuncAttributeMaxDynamicSharedMemorySize, SMEM_BYTES);
        attr_set = true;
    }

    prep_kernel<<<256, 128>>>(x, weight);
    tversky_main_kernel<<<GRID_MAIN, 256, SMEM_BYTES>>>();
    finalize_kernel<<<(B_DIM * P_DIM / 4) / 256, 256>>>(bias, alpha, beta, out);
}